// round 7
// baseline (speedup 1.0000x reference)
#include <cuda_runtime.h>

// x: (B=64, NU=32, IC=256, UNIT=128) fp32, contiguous.
// Reference reinterprets flat buffer as (B, IC, NU, UNIT):
//   u_hat[b,i,j,u] = x_flat[b*1048576 + i*4096 + j*128 + u]
// s[b,j,u] = (1/256) * sum_i u_hat[b,i,j,u]; then squash over u (128 elems).
// Output: (B, NU, UNIT) = 262144 fp32.
//
// R7: two-kernel PERFECTLY SEQUENTIAL streaming experiment. All prior
// variants read 512B-1KB columns at 16KB stride and plateau at 6.3-6.5TB/s.
// Kernel 1: one block per (b, slab-of-32-rows) = 512 blocks; each block
// streams a contiguous 512KB slab front-to-back. Thread t owns float4 row
// positions {t, t+256, t+512, t+768} (fixed (j,u) slots) in 4 register
// accumulators -> 16KB partial per block into __device__ scratch.
// Kernel 2: warp per (b,j) sums the 8 slab partials + squash + store.
// Extra traffic: +16MB (6%) vs +hoped ~12% bandwidth from page locality.

static constexpr int B_DIM   = 64;
static constexpr int SLABS   = 8;                 // slabs per b
static constexpr int ROWS    = 256 / SLABS;       // 32 rows per slab
static constexpr int ROW4    = 4096 / 4;          // float4 per row = 1024
static constexpr int K1_BLOCKS  = B_DIM * SLABS;  // 512
static constexpr int K1_THREADS = 256;

// 64 b * 8 slabs * 1024 float4 partials
__device__ float4 g_partial[K1_BLOCKS * ROW4];

__global__ __launch_bounds__(K1_THREADS)
void capsule_partial_kernel(const float4* __restrict__ x4) {
    const int blk = blockIdx.x;                   // b*8 + slab
    const int tid = threadIdx.x;

    // base float4 index of this slab: b*262144 + slab*32*1024
    const long base4 = (long)blk * (ROWS * ROW4);

    float4 a0 = make_float4(0.f, 0.f, 0.f, 0.f);
    float4 a1 = make_float4(0.f, 0.f, 0.f, 0.f);
    float4 a2 = make_float4(0.f, 0.f, 0.f, 0.f);
    float4 a3 = make_float4(0.f, 0.f, 0.f, 0.f);

#pragma unroll 4
    for (int i = 0; i < ROWS; i++) {
        const float4* p = x4 + base4 + i * ROW4 + tid;
        float4 v0 = __ldcs(p);
        float4 v1 = __ldcs(p + 256);
        float4 v2 = __ldcs(p + 512);
        float4 v3 = __ldcs(p + 768);
        a0.x += v0.x; a0.y += v0.y; a0.z += v0.z; a0.w += v0.w;
        a1.x += v1.x; a1.y += v1.y; a1.z += v1.z; a1.w += v1.w;
        a2.x += v2.x; a2.y += v2.y; a2.z += v2.z; a2.w += v2.w;
        a3.x += v3.x; a3.y += v3.y; a3.z += v3.z; a3.w += v3.w;
    }

    float4* out = g_partial + (long)blk * ROW4;
    out[tid      ] = a0;
    out[tid + 256] = a1;
    out[tid + 512] = a2;
    out[tid + 768] = a3;
}

// Kernel 2: 256 blocks x 256 threads; warp w handles group g = blk*8 + w.
static constexpr int K2_BLOCKS  = 256;
static constexpr int K2_THREADS = 256;

__global__ __launch_bounds__(K2_THREADS)
void capsule_squash_kernel(float4* __restrict__ out4) {
    const int warp = threadIdx.x >> 5;
    const int lane = threadIdx.x & 31;
    const int g = blockIdx.x * 8 + warp;          // group = b*32 + j
    const int b = g >> 5;
    const int j = g & 31;

    // partial for (b, slab s) at float4 position j*32 + lane
    const float4* base = g_partial + (long)(b * SLABS) * ROW4 + j * 32 + lane;

    float4 t = make_float4(0.f, 0.f, 0.f, 0.f);
#pragma unroll
    for (int s = 0; s < SLABS; s++) {
        float4 p = base[s * ROW4];
        t.x += p.x; t.y += p.y; t.z += p.z; t.w += p.w;
    }

    const float c = 1.0f / 256.0f;
    t.x *= c; t.y *= c; t.z *= c; t.w *= c;

    // mag_sq over the 128-element unit dim (warp-wide)
    float sq = t.x * t.x + t.y * t.y + t.z * t.z + t.w * t.w;
#pragma unroll
    for (int off = 16; off > 0; off >>= 1)
        sq += __shfl_xor_sync(0xffffffffu, sq, off);

    const float mag   = sqrtf(sq);
    const float scale = sq / (1.0f + sq) / (mag + 1e-5f);

    out4[g * 32 + lane] = make_float4(t.x * scale, t.y * scale,
                                      t.z * scale, t.w * scale);
}

extern "C" void kernel_launch(void* const* d_in, const int* in_sizes, int n_in,
                              void* d_out, int out_size) {
    const float4* x4 = (const float4*)d_in[0];
    float4* out4 = (float4*)d_out;
    capsule_partial_kernel<<<K1_BLOCKS, K1_THREADS>>>(x4);
    capsule_squash_kernel<<<K2_BLOCKS, K2_THREADS>>>(out4);
}

// round 8
// speedup vs baseline: 1.1725x; 1.1725x over previous
#include <cuda_runtime.h>

// x: (B=64, NU=32, IC=256, UNIT=128) fp32, contiguous.
// Reference reinterprets flat buffer as (B, IC, NU, UNIT):
//   u_hat[b,i,j,u] = x_flat[b*1048576 + i*4096 + j*128 + u]
// s[b,j,u] = (1/256) * sum_i u_hat[b,i,j,u]; then squash over u (128 elems).
// Output: (B, NU, UNIT) = 262144 fp32.
//
// R8: R5 structure (one 128-thread block per (b,j) group, 2048 blocks,
// warps i-interleaved i = warp + 4k, __ldcs streaming) with the register
// cap RELAXED: __launch_bounds__(128, 8) allows 64 regs/thread so ptxas can
// front-batch the unrolled loads (R5's (128,16) forced regs=32 and choked
// MLP_eff). Two independent accumulators break the FADD dependency chain.
// R6 proved occupancy is not binding (41% occ == same BW), so trading
// residency (16 -> 8 blocks/SM) for in-flight loads is free.
// R7 falsified the sequential-stream hypothesis: ~6.4 TB/s is the path
// ceiling; this round targets only the remaining latency-exposure slack.

static constexpr int IC       = 256;
static constexpr int GROUPS   = 64 * 32;        // 2048 blocks
static constexpr int STRIDE4  = 4096 / 4;       // i-stride in float4 units
static constexpr int THREADS  = 128;            // 4 warps/block
static constexpr int IC_PER_W = IC / 4;         // 64 rows per warp

__global__ __launch_bounds__(THREADS, 8)
void capsule_squash_kernel(const float4* __restrict__ x4,
                           float4* __restrict__ out4) {
    const int g    = blockIdx.x;                // group = b*32 + j
    const int warp = threadIdx.x >> 5;
    const int lane = threadIdx.x & 31;

    const int b = g >> 5;
    const int j = g & 31;
    // warp w reads rows i = w, w+4, w+8, ... (interleaved across warps)
    const int base4 = b * (1048576 / 4) + j * (128 / 4) + lane
                    + warp * STRIDE4;

    float4 sA = make_float4(0.f, 0.f, 0.f, 0.f);
    float4 sB = make_float4(0.f, 0.f, 0.f, 0.f);

#pragma unroll 8
    for (int k = 0; k < IC_PER_W; k += 2) {
        float4 vA = __ldcs(&x4[base4 + (k    ) * (4 * STRIDE4)]);
        float4 vB = __ldcs(&x4[base4 + (k + 1) * (4 * STRIDE4)]);
        sA.x += vA.x; sA.y += vA.y; sA.z += vA.z; sA.w += vA.w;
        sB.x += vB.x; sB.y += vB.y; sB.z += vB.z; sB.w += vB.w;
    }
    float4 s = make_float4(sA.x + sB.x, sA.y + sB.y,
                           sA.z + sB.z, sA.w + sB.w);

    __shared__ float4 part[4][32];
    part[warp][lane] = s;
    __syncthreads();

    if (warp == 0) {
        float4 t = part[0][lane];
#pragma unroll
        for (int w = 1; w < 4; w++) {
            float4 p = part[w][lane];
            t.x += p.x; t.y += p.y; t.z += p.z; t.w += p.w;
        }
        const float c = 1.0f / 256.0f;
        t.x *= c; t.y *= c; t.z *= c; t.w *= c;

        // mag_sq over the 128-element unit dim (warp-wide)
        float sq = t.x * t.x + t.y * t.y + t.z * t.z + t.w * t.w;
#pragma unroll
        for (int off = 16; off > 0; off >>= 1)
            sq += __shfl_xor_sync(0xffffffffu, sq, off);

        const float mag   = sqrtf(sq);
        const float scale = sq / (1.0f + sq) / (mag + 1e-5f);

        out4[g * 32 + lane] = make_float4(t.x * scale, t.y * scale,
                                          t.z * scale, t.w * scale);
    }
}

extern "C" void kernel_launch(void* const* d_in, const int* in_sizes, int n_in,
                              void* d_out, int out_size) {
    const float4* x4 = (const float4*)d_in[0];
    float4* out4 = (float4*)d_out;
    capsule_squash_kernel<<<GROUPS, THREADS>>>(x4, out4);
}